// round 1
// baseline (speedup 1.0000x reference)
#include <cuda_runtime.h>

#define BB 2
#define NH 8
#define TT 192
#define HD 64
#define CC 512
#define BH 16            // BB*NH
#define NTILE 6          // TT/32
#define NPAIR 21         // NTILE*(NTILE+1)/2
#define SCALE 0.125f     // 1/sqrt(64)

// persistent device scratch (no allocations allowed)
__device__ __align__(16) float g_q [BH*TT*HD];
__device__ __align__(16) float g_k1[BH*TT*HD];
__device__ __align__(16) float g_k2[BH*TT*HD];
__device__ __align__(16) float g_Np[NTILE*BH*TT*HD];  // numerator partials per j-tile slab
__device__ __align__(16) float g_Zp[BH*NPAIR];        // Z partials per block
__device__ __align__(16) float g_y [BB*TT*CC];        // normalized y before final proj

// ---------------------------------------------------------------------------
__global__ void zero_kernel()
{
    int idx = blockIdx.x * 256 + threadIdx.x;
    if (idx < NTILE*BH*TT*HD) g_Np[idx] = 0.f;
}

// ---------------------------------------------------------------------------
// projections: q = x@W0^T, k1 = x@W1^T, k2 = x@W2^T, stored [bh][t][d]
__global__ __launch_bounds__(256)
void proj_kernel(const float* __restrict__ x, const float* __restrict__ W0,
                 const float* __restrict__ W1, const float* __restrict__ W2)
{
    __shared__ float xs[32][33];
    __shared__ float ws[32][33];
    const float* W   = (blockIdx.z == 0) ? W0 : (blockIdx.z == 1) ? W1 : W2;
    float*       dst = (blockIdx.z == 0) ? g_q : (blockIdx.z == 1) ? g_k1 : g_k2;
    const int tid = threadIdx.x;
    const int tx = tid & 15, ty = tid >> 4;
    const int row0 = blockIdx.y * 32, col0 = blockIdx.x * 32;
    float acc[2][2] = {{0.f,0.f},{0.f,0.f}};
    for (int k0 = 0; k0 < CC; k0 += 32) {
        #pragma unroll
        for (int e = 0; e < 4; ++e) {
            int l = tid + 256*e;
            int r = l >> 5, kk = l & 31;
            xs[r][kk] = x[(row0 + r)*CC + k0 + kk];
            ws[r][kk] = W[(col0 + r)*CC + k0 + kk];
        }
        __syncthreads();
        #pragma unroll
        for (int kk = 0; kk < 32; ++kk) {
            float a0 = xs[(ty<<1)  ][kk], a1 = xs[(ty<<1)+1][kk];
            float b0 = ws[(tx<<1)  ][kk], b1 = ws[(tx<<1)+1][kk];
            acc[0][0] += a0*b0; acc[0][1] += a0*b1;
            acc[1][0] += a1*b0; acc[1][1] += a1*b1;
        }
        __syncthreads();
    }
    #pragma unroll
    for (int a = 0; a < 2; ++a)
        #pragma unroll
        for (int b2 = 0; b2 < 2; ++b2) {
            int row = row0 + (ty<<1) + a;
            int col = col0 + (tx<<1) + b2;
            int b = row / TT, t = row - b*TT;
            int h = col >> 6, d = col & 63;
            dst[((b*NH + h)*TT + t)*HD + d] = acc[a][b2];
        }
}

// ---------------------------------------------------------------------------
// fused trilinear scores + exp + j-fold + PV.
// block = (bh, i-tile, j-tile<=i-tile); 336 blocks, biggest j-tiles first.
__global__ __launch_bounds__(256)
void attn_kernel()
{
    __shared__ __align__(16) float qT [HD][32];
    __shared__ __align__(16) float k1T[HD][32];
    __shared__ __align__(16) float k2T[HD][32];
    __shared__ __align__(16) float k2n[32][HD];
    __shared__ __align__(16) float Qs [32][32];
    __shared__ float zred[8];

    const int bh = blockIdx.x & 15;
    const int p  = blockIdx.x >> 4;
    // p ordered by tj descending: counts per tj are (NTILE - tj)
    int tj = NTILE - 1, start = 0, cnt = 1;
    while (p >= start + cnt) { start += cnt; --tj; ++cnt; }
    const int ti = tj + (p - start);
    const int i0 = ti * 32, j0 = tj * 32;
    const int tid = threadIdx.x;
    const int ii = tid >> 4, jj = tid & 15;
    const bool maskJ = (ti == tj);

    // load q / k1 tiles transposed into smem
    {
        const float* qg  = g_q  + (bh*TT + i0)*HD;
        const float* k1g = g_k1 + (bh*TT + j0)*HD;
        for (int l = tid; l < 512; l += 256) {
            int r = l >> 4, dq = (l & 15) << 2;
            float4 v = *(const float4*)(qg + r*HD + dq);
            qT[dq+0][r]=v.x; qT[dq+1][r]=v.y; qT[dq+2][r]=v.z; qT[dq+3][r]=v.w;
            float4 u = *(const float4*)(k1g + r*HD + dq);
            k1T[dq+0][r]=u.x; k1T[dq+1][r]=u.y; k1T[dq+2][r]=u.z; k1T[dq+3][r]=u.w;
        }
    }

    const int pv_i = tid >> 3;
    const int pv_d = (tid & 7) << 3;
    float nacc[8] = {0.f,0.f,0.f,0.f,0.f,0.f,0.f,0.f};
    float zacc = 0.f;

    for (int kc = 0; kc <= tj; ++kc) {
        __syncthreads();   // protect k2 tiles / Qs reuse from previous iteration
        {
            const float* k2g = g_k2 + (bh*TT + kc*32)*HD;
            for (int l = tid; l < 512; l += 256) {
                int r = l >> 4, dq = (l & 15) << 2;
                float4 v = *(const float4*)(k2g + r*HD + dq);
                *(float4*)&k2n[r][dq] = v;
                k2T[dq+0][r]=v.x; k2T[dq+1][r]=v.y; k2T[dq+2][r]=v.z; k2T[dq+3][r]=v.w;
            }
        }
        __syncthreads();
        const bool maskK = (kc == tj);

        #pragma unroll 1
        for (int s = 0; s < 4; ++s) {
            float acc[2][2][8];
            #pragma unroll
            for (int a=0;a<2;a++)
                #pragma unroll
                for (int b=0;b<2;b++)
                    #pragma unroll
                    for (int c=0;c<8;c++) acc[a][b][c]=0.f;

            const float* qp  = &qT [0][ii<<1];
            const float* k1p = &k1T[0][jj<<1];
            const float* k2p = &k2T[0][s<<3];
            #pragma unroll 8
            for (int d = 0; d < HD; ++d) {
                float2 qv  = *(const float2*)(qp  + d*32);
                float2 k1v = *(const float2*)(k1p + d*32);
                float4 ka  = *(const float4*)(k2p + d*32);
                float4 kb  = *(const float4*)(k2p + d*32 + 4);
                float w00 = qv.x*k1v.x, w01 = qv.x*k1v.y;
                float w10 = qv.y*k1v.x, w11 = qv.y*k1v.y;
                float kv[8] = {ka.x,ka.y,ka.z,ka.w,kb.x,kb.y,kb.z,kb.w};
                #pragma unroll
                for (int c = 0; c < 8; ++c) {
                    acc[0][0][c] += w00*kv[c];
                    acc[0][1][c] += w01*kv[c];
                    acc[1][0][c] += w10*kv[c];
                    acc[1][1][c] += w11*kv[c];
                }
            }

            // mask + exp + fold over this thread's 2 j's
            const int kbase = kc*32 + (s<<3);
            float qsum[2][8];
            #pragma unroll
            for (int a = 0; a < 2; ++a) {
                const int ig = i0 + (ii<<1) + a;
                #pragma unroll
                for (int c = 0; c < 8; ++c) {
                    const int kg = kbase + c;
                    float psum = 0.f;
                    #pragma unroll
                    for (int b = 0; b < 2; ++b) {
                        const int jg = j0 + (jj<<1) + b;
                        bool v = (!maskJ || jg <= ig) && (!maskK || kg <= jg);
                        float pe = v ? __expf(acc[a][b][c]*SCALE) : 0.f;
                        psum += pe;
                    }
                    zacc += psum;
                    qsum[a][c] = psum;
                }
            }
            // butterfly-reduce over the 16 jj lanes (stays inside each half-warp)
            #pragma unroll
            for (int m = 8; m >= 1; m >>= 1)
                #pragma unroll
                for (int a = 0; a < 2; ++a)
                    #pragma unroll
                    for (int c = 0; c < 8; ++c)
                        qsum[a][c] += __shfl_xor_sync(0xffffffffu, qsum[a][c], m);
            if (jj == 0) {
                #pragma unroll
                for (int a = 0; a < 2; ++a)
                    #pragma unroll
                    for (int c = 0; c < 8; ++c)
                        Qs[(ii<<1)+a][(s<<3)+c] = qsum[a][c];
            }
        }
        __syncthreads();

        // PV chunk: nacc[i, d0..d0+7] += sum_k Qs[i,k] * k2n[k,d]
        #pragma unroll 8
        for (int k = 0; k < 32; ++k) {
            float qv = Qs[pv_i][k];
            float4 v0 = *(const float4*)&k2n[k][pv_d];
            float4 v1 = *(const float4*)&k2n[k][pv_d+4];
            nacc[0]+=qv*v0.x; nacc[1]+=qv*v0.y; nacc[2]+=qv*v0.z; nacc[3]+=qv*v0.w;
            nacc[4]+=qv*v1.x; nacc[5]+=qv*v1.y; nacc[6]+=qv*v1.z; nacc[7]+=qv*v1.w;
        }
    }

    // write numerator partial (unique writer per (tj-slab, bh, row))
    {
        float* np = g_Np + ((tj*BH + bh)*TT + i0 + pv_i)*HD + pv_d;
        #pragma unroll
        for (int c = 0; c < 8; ++c) np[c] = nacc[c];
    }
    // Z partial: block-reduce
    #pragma unroll
    for (int m = 16; m >= 1; m >>= 1)
        zacc += __shfl_xor_sync(0xffffffffu, zacc, m);
    if ((tid & 31) == 0) zred[tid >> 5] = zacc;
    __syncthreads();
    if (tid == 0) {
        float z = 0.f;
        #pragma unroll
        for (int w = 0; w < 8; ++w) z += zred[w];
        g_Zp[bh*NPAIR + p] = z;
    }
}

// ---------------------------------------------------------------------------
// y[b,t,h*64+d] = (sum of slab partials) / Z[bh]
__global__ __launch_bounds__(256)
void finalize_y()
{
    __shared__ float invZ[BH];
    const int tid = threadIdx.x;
    if (tid < BH) {
        float z = 0.f;
        #pragma unroll
        for (int pp = 0; pp < NPAIR; ++pp) z += g_Zp[tid*NPAIR + pp];
        invZ[tid] = 1.f / z;
    }
    __syncthreads();
    int idx = blockIdx.x * 256 + tid;     // < BB*TT*CC
    int c   = idx & (CC-1);
    int row = idx >> 9;
    int b = row / TT, t = row - b*TT;
    int h = c >> 6, d = c & 63;
    int bh = b*NH + h;
    float y = 0.f;
    #pragma unroll
    for (int s6 = 0; s6 < NTILE; ++s6)
        y += g_Np[((s6*BH + bh)*TT + t)*HD + d];
    g_y[idx] = y * invZ[bh];
}

// ---------------------------------------------------------------------------
// out = y @ Wp^T
__global__ __launch_bounds__(256)
void out_kernel(const float* __restrict__ Wp, float* __restrict__ out)
{
    __shared__ float ys[32][33];
    __shared__ float ws[32][33];
    const int tid = threadIdx.x;
    const int tx = tid & 15, ty = tid >> 4;
    const int row0 = blockIdx.y * 32, col0 = blockIdx.x * 32;
    float acc[2][2] = {{0.f,0.f},{0.f,0.f}};
    for (int k0 = 0; k0 < CC; k0 += 32) {
        #pragma unroll
        for (int e = 0; e < 4; ++e) {
            int l = tid + 256*e;
            int r = l >> 5, kk = l & 31;
            ys[r][kk] = g_y[(row0 + r)*CC + k0 + kk];
            ws[r][kk] = Wp[(col0 + r)*CC + k0 + kk];
        }
        __syncthreads();
        #pragma unroll
        for (int kk = 0; kk < 32; ++kk) {
            float a0 = ys[(ty<<1)  ][kk], a1 = ys[(ty<<1)+1][kk];
            float b0 = ws[(tx<<1)  ][kk], b1 = ws[(tx<<1)+1][kk];
            acc[0][0] += a0*b0; acc[0][1] += a0*b1;
            acc[1][0] += a1*b0; acc[1][1] += a1*b1;
        }
        __syncthreads();
    }
    #pragma unroll
    for (int a = 0; a < 2; ++a)
        #pragma unroll
        for (int b2 = 0; b2 < 2; ++b2)
            out[(row0 + (ty<<1) + a)*CC + col0 + (tx<<1) + b2] = acc[a][b2];
}

// ---------------------------------------------------------------------------
extern "C" void kernel_launch(void* const* d_in, const int* in_sizes, int n_in,
                              void* d_out, int out_size)
{
    const float* x  = (const float*)d_in[0];
    const float* W0 = (const float*)d_in[1];
    const float* W1 = (const float*)d_in[2];
    const float* W2 = (const float*)d_in[3];
    const float* Wp = (const float*)d_in[4];
    float* out = (float*)d_out;

    zero_kernel<<<(NTILE*BH*TT*HD + 255)/256, 256>>>();
    dim3 pg(CC/32, (BB*TT)/32, 3);
    proj_kernel<<<pg, 256>>>(x, W0, W1, W2);
    attn_kernel<<<NPAIR*BH, 256>>>();
    finalize_y<<<(BB*TT*CC)/256, 256>>>();
    dim3 og(CC/32, (BB*TT)/32);
    out_kernel<<<og, 256>>>(Wp, out);
}

// round 3
// speedup vs baseline: 2.0648x; 2.0648x over previous
#include <cuda_runtime.h>
#include <cuda_fp16.h>
#include <stdint.h>

#define BB 2
#define NH 8
#define TT 192
#define HD 64
#define CC 512
#define BH 16            // BB*NH
#define NTILE 6          // TT/32
#define NPAIR 21         // NTILE*(NTILE+1)/2
#define SCALE 0.125f     // 1/sqrt(64)

// persistent device scratch (no allocations allowed)
__device__ __align__(16) float g_q [BH*TT*HD];
__device__ __align__(16) float g_k1[BH*TT*HD];
__device__ __align__(16) float g_k2[BH*TT*HD];
__device__ __align__(16) float g_Np[NTILE*BH*TT*HD];  // numerator partials per j-tile slab
__device__ __align__(16) float g_Zp[BH*NPAIR];        // Z partials per block
__device__ __align__(16) float g_y [BB*TT*CC];        // normalized y before final proj

// ---------------------------------------------------------------------------
__global__ void zero_kernel()
{
    int idx = blockIdx.x * 256 + threadIdx.x;
    if (idx < NTILE*BH*TT*HD) g_Np[idx] = 0.f;
}

// ---------------------------------------------------------------------------
// projections: q = x@W0^T, k1 = x@W1^T, k2 = x@W2^T, stored [bh][t][d]
__global__ __launch_bounds__(256)
void proj_kernel(const float* __restrict__ x, const float* __restrict__ W0,
                 const float* __restrict__ W1, const float* __restrict__ W2)
{
    __shared__ float xs[32][33];
    __shared__ float ws[32][33];
    const float* W   = (blockIdx.z == 0) ? W0 : (blockIdx.z == 1) ? W1 : W2;
    float*       dst = (blockIdx.z == 0) ? g_q : (blockIdx.z == 1) ? g_k1 : g_k2;
    const int tid = threadIdx.x;
    const int tx = tid & 15, ty = tid >> 4;
    const int row0 = blockIdx.y * 32, col0 = blockIdx.x * 32;
    float acc[2][2] = {{0.f,0.f},{0.f,0.f}};
    for (int k0 = 0; k0 < CC; k0 += 32) {
        #pragma unroll
        for (int e = 0; e < 4; ++e) {
            int l = tid + 256*e;
            int r = l >> 5, kk = l & 31;
            xs[r][kk] = x[(row0 + r)*CC + k0 + kk];
            ws[r][kk] = W[(col0 + r)*CC + k0 + kk];
        }
        __syncthreads();
        #pragma unroll
        for (int kk = 0; kk < 32; ++kk) {
            float a0 = xs[(ty<<1)  ][kk], a1 = xs[(ty<<1)+1][kk];
            float b0 = ws[(tx<<1)  ][kk], b1 = ws[(tx<<1)+1][kk];
            acc[0][0] += a0*b0; acc[0][1] += a0*b1;
            acc[1][0] += a1*b0; acc[1][1] += a1*b1;
        }
        __syncthreads();
    }
    #pragma unroll
    for (int a = 0; a < 2; ++a)
        #pragma unroll
        for (int b2 = 0; b2 < 2; ++b2) {
            int row = row0 + (ty<<1) + a;
            int col = col0 + (tx<<1) + b2;
            int b = row / TT, t = row - b*TT;
            int h = col >> 6, d = col & 63;
            dst[((b*NH + h)*TT + t)*HD + d] = acc[a][b2];
        }
}

// ---------------------------------------------------------------------------
// HMMA helpers
__device__ __forceinline__ unsigned int pkh2(float a, float b)
{
    __half2 h = __floats2half2_rn(a, b);
    return *reinterpret_cast<unsigned int*>(&h);
}

__device__ __forceinline__ void mma16816(float* d, const unsigned int* a, const unsigned int* b)
{
    asm volatile(
        "mma.sync.aligned.m16n8k16.row.col.f32.f16.f16.f32 "
        "{%0,%1,%2,%3}, {%4,%5,%6,%7}, {%8,%9}, {%0,%1,%2,%3};\n"
        : "+f"(d[0]), "+f"(d[1]), "+f"(d[2]), "+f"(d[3])
        : "r"(a[0]), "r"(a[1]), "r"(a[2]), "r"(a[3]), "r"(b[0]), "r"(b[1]));
}

// one 32-token k-chunk: mma, mask+exp, j-fold, PV — all within one warp.
// MJ: ti==tj (j<=i mask active); MK: kc==tj (k<=j mask active).
template<bool MJ, bool MK>
__device__ __forceinline__ void do_chunk(
    int n0, int ig, int j0, int g, int q2, int lane,
    const unsigned int (&afr)[2][4][4], const __half (*k2s)[72],
    float& zacc, float& nacc0, float& nacc1)
{
    #pragma unroll
    for (int nt = 0; nt < 4; ++nt) {
        // whole 8-token group above i on corner-diagonal chunks: fully masked
        if (MJ && MK && (n0 + nt*8) > ig) continue;
        const int tok = n0 + nt*8 + g;
        unsigned int bfr[4][2];
        #pragma unroll
        for (int ks = 0; ks < 4; ++ks) {
            bfr[ks][0] = *(const unsigned int*)&k2s[tok][ks*16 + q2];
            bfr[ks][1] = *(const unsigned int*)&k2s[tok][ks*16 + q2 + 8];
        }
        float Qf0 = 0.f, Qf1 = 0.f;
        #pragma unroll
        for (int mt = 0; mt < 2; ++mt) {
            if (MJ && (j0 + mt*16) > ig) continue;  // whole 16-row group above i
            float acc[4] = {0.f, 0.f, 0.f, 0.f};
            #pragma unroll
            for (int ks = 0; ks < 4; ++ks) mma16816(acc, afr[mt][ks], bfr[ks]);
            const int jlo = j0 + mt*16 + g, jhi = jlo + 8;
            const int k0  = n0 + nt*8 + q2, k1 = k0 + 1;
            bool v0 = (!MJ || jlo <= ig) && (!MK || k0 <= jlo);
            bool v1 = (!MJ || jlo <= ig) && (!MK || k1 <= jlo);
            bool v2 = (!MJ || jhi <= ig) && (!MK || k0 <= jhi);
            bool v3 = (!MJ || jhi <= ig) && (!MK || k1 <= jhi);
            float p0 = v0 ? __expf(acc[0]*SCALE) : 0.f;
            float p1 = v1 ? __expf(acc[1]*SCALE) : 0.f;
            float p2 = v2 ? __expf(acc[2]*SCALE) : 0.f;
            float p3 = v3 ? __expf(acc[3]*SCALE) : 0.f;
            zacc += (p0 + p1) + (p2 + p3);
            Qf0 += p0 + p2;
            Qf1 += p1 + p3;
        }
        // fold across the 8 j row-groups (lanes differing in bits 2..4)
        #pragma unroll
        for (int m = 4; m <= 16; m <<= 1) {
            Qf0 += __shfl_xor_sync(0xffffffffu, Qf0, m);
            Qf1 += __shfl_xor_sync(0xffffffffu, Qf1, m);
        }
        // PV for this nt's 8 tokens: nacc[d] += Q[k] * k2[k][d]
        #pragma unroll
        for (int kk = 0; kk < 8; ++kk) {
            float qv = __shfl_sync(0xffffffffu, (kk & 1) ? Qf1 : Qf0, kk >> 1);
            __half2 hv = *(const __half2*)&k2s[n0 + nt*8 + kk][2*lane];
            float2 fv = __half22float2(hv);
            nacc0 += qv * fv.x;
            nacc1 += qv * fv.y;
        }
    }
}

// ---------------------------------------------------------------------------
// fused trilinear scores (HMMA) + exp + j-fold + PV.
// block = (bh, i-tile, j-tile<=i-tile); 336 blocks. Warp w owns i = isub*8+w.
__global__ __launch_bounds__(256)
void attn_kernel()
{
    __shared__ float  qs [32][65];
    __shared__ float  k1s[32][65];
    __shared__ __half k2s[192][72];
    __shared__ float  zred[8];

    const int bh = blockIdx.x & 15;
    const int p  = blockIdx.x >> 4;
    int tj = NTILE - 1, start = 0, cnt = 1;
    while (p >= start + cnt) { start += cnt; --tj; ++cnt; }
    const int ti = tj + (p - start);
    const int i0 = ti * 32, j0 = tj * 32;
    const int tid  = threadIdx.x;
    const int w    = tid >> 5, lane = tid & 31;
    const int g    = lane >> 2, q2 = (lane & 3) << 1;
    const bool diag = (ti == tj);

    // load q/k1 tiles fp32; k2 (all tokens 0..(tj+1)*32) as fp16
    {
        const float* qg  = g_q  + (bh*TT + i0)*HD;
        const float* k1g = g_k1 + (bh*TT + j0)*HD;
        for (int l = tid; l < 32*64; l += 256) {
            int r = l >> 6, d = l & 63;
            qs[r][d]  = qg[r*HD + d];
            k1s[r][d] = k1g[r*HD + d];
        }
        const int ntok = (tj + 1) * 32;
        const float* k2g = g_k2 + bh*TT*HD;
        for (int l = tid; l < ntok*16; l += 256) {
            int r = l >> 4, c4 = (l & 15) << 2;
            float4 v = *(const float4*)(k2g + r*HD + c4);
            *(__half2*)&k2s[r][c4]     = __floats2half2_rn(v.x, v.y);
            *(__half2*)&k2s[r][c4 + 2] = __floats2half2_rn(v.z, v.w);
        }
    }
    __syncthreads();

    float zacc = 0.f;

    for (int isub = 0; isub < 4; ++isub) {
        const int il = isub*8 + w;      // this warp's i within the tile
        const int ig = i0 + il;

        // build A fragments in registers: W[j,d] = q[i,d] * k1[j,d] (fp16)
        unsigned int afr[2][4][4];
        #pragma unroll
        for (int mt = 0; mt < 2; ++mt) {
            const int jlo = mt*16 + g, jhi = jlo + 8;
            #pragma unroll
            for (int ks = 0; ks < 4; ++ks) {
                const int d0 = ks*16 + q2;
                float qa = qs[il][d0],   qb = qs[il][d0+1];
                float qc = qs[il][d0+8], qd = qs[il][d0+9];
                afr[mt][ks][0] = pkh2(qa*k1s[jlo][d0],   qb*k1s[jlo][d0+1]);
                afr[mt][ks][1] = pkh2(qa*k1s[jhi][d0],   qb*k1s[jhi][d0+1]);
                afr[mt][ks][2] = pkh2(qc*k1s[jlo][d0+8], qd*k1s[jlo][d0+9]);
                afr[mt][ks][3] = pkh2(qc*k1s[jhi][d0+8], qd*k1s[jhi][d0+9]);
            }
        }

        float nacc0 = 0.f, nacc1 = 0.f;
        for (int kc = 0; kc <= tj; ++kc) {
            const int n0 = kc * 32;
            const bool mk = (kc == tj);
            if (diag) {
                if (mk) do_chunk<true ,true >(n0, ig, j0, g, q2, lane, afr, k2s, zacc, nacc0, nacc1);
                else    do_chunk<true ,false>(n0, ig, j0, g, q2, lane, afr, k2s, zacc, nacc0, nacc1);
            } else {
                if (mk) do_chunk<false,true >(n0, ig, j0, g, q2, lane, afr, k2s, zacc, nacc0, nacc1);
                else    do_chunk<false,false>(n0, ig, j0, g, q2, lane, afr, k2s, zacc, nacc0, nacc1);
            }
        }
        // write numerator partial row (unique writer per (tj-slab, bh, i))
        float* np = g_Np + ((tj*BH + bh)*TT + ig)*HD + 2*lane;
        np[0] = nacc0;
        np[1] = nacc1;
    }

    // Z partial: block-reduce
    #pragma unroll
    for (int m = 16; m >= 1; m >>= 1)
        zacc += __shfl_xor_sync(0xffffffffu, zacc, m);
    if (lane == 0) zred[w] = zacc;
    __syncthreads();
    if (tid == 0) {
        float z = 0.f;
        #pragma unroll
        for (int ww = 0; ww < 8; ++ww) z += zred[ww];
        g_Zp[bh*NPAIR + p] = z;
    }
}

// ---------------------------------------------------------------------------
// y[b,t,h*64+d] = (sum of slab partials) / Z[bh]
__global__ __launch_bounds__(256)
void finalize_y()
{
    __shared__ float invZ[BH];
    const int tid = threadIdx.x;
    if (tid < BH) {
        float z = 0.f;
        #pragma unroll
        for (int pp = 0; pp < NPAIR; ++pp) z += g_Zp[tid*NPAIR + pp];
        invZ[tid] = 1.f / z;
    }
    __syncthreads();
    int idx = blockIdx.x * 256 + tid;     // < BB*TT*CC
    int c   = idx & (CC-1);
    int row = idx >> 9;
    int b = row / TT, t = row - b*TT;
    int h = c >> 6, d = c & 63;
    int bh = b*NH + h;
    float y = 0.f;
    #pragma unroll
    for (int s6 = 0; s6 < NTILE; ++s6)
        y += g_Np[((s6*BH + bh)*TT + t)*HD + d];
    g_y[idx] = y * invZ[bh];
}

// ---------------------------------------------------------------------------
// out = y @ Wp^T
__global__ __launch_bounds__(256)
void out_kernel(const float* __restrict__ Wp, float* __restrict__ out)
{
    __shared__ float ys[32][33];
    __shared__ float ws[32][33];
    const int tid = threadIdx.x;
    const int tx = tid & 15, ty = tid >> 4;
    const int row0 = blockIdx.y * 32, col0 = blockIdx.x * 32;
    float acc[2][2] = {{0.f,0.f},{0.f,0.f}};
    for (int k0 = 0; k0 < CC; k0 += 32) {
        #pragma unroll
        for (int e = 0; e < 4; ++e) {
            int l = tid + 256*e;
            int r = l >> 5, kk = l & 31;
            ys[r][kk] = g_y[(row0 + r)*CC + k0 + kk];
            ws[r][kk] = Wp[(col0 + r)*CC + k0 + kk];
        }
        __syncthreads();
        #pragma unroll
        for (int kk = 0; kk < 32; ++kk) {
            float a0 = ys[(ty<<1)  ][kk], a1 = ys[(ty<<1)+1][kk];
            float b0 = ws[(tx<<1)  ][kk], b1 = ws[(tx<<1)+1][kk];
            acc[0][0] += a0*b0; acc[0][1] += a0*b1;
            acc[1][0] += a1*b0; acc[1][1] += a1*b1;
        }
        __syncthreads();
    }
    #pragma unroll
    for (int a = 0; a < 2; ++a)
        #pragma unroll
        for (int b2 = 0; b2 < 2; ++b2)
            out[(row0 + (ty<<1) + a)*CC + col0 + (tx<<1) + b2] = acc[a][b2];
}

// ---------------------------------------------------------------------------
extern "C" void kernel_launch(void* const* d_in, const int* in_sizes, int n_in,
                              void* d_out, int out_size)
{
    const float* x  = (const float*)d_in[0];
    const float* W0 = (const float*)d_in[1];
    const float* W1 = (const float*)d_in[2];
    const float* W2 = (const float*)d_in[3];
    const float* Wp = (const float*)d_in[4];
    float* out = (float*)d_out;

    zero_kernel<<<(NTILE*BH*TT*HD + 255)/256, 256>>>();
    dim3 pg(CC/32, (BB*TT)/32, 3);
    proj_kernel<<<pg, 256>>>(x, W0, W1, W2);
    attn_kernel<<<NPAIR*BH, 256>>>();
    finalize_y<<<(BB*TT*CC)/256, 256>>>();
    dim3 og(CC/32, (BB*TT)/32);
    out_kernel<<<og, 256>>>(Wp, out);
}

// round 4
// speedup vs baseline: 2.1787x; 1.0552x over previous
#include <cuda_runtime.h>
#include <cuda_fp16.h>
#include <stdint.h>

#define BB 2
#define NH 8
#define TT 192
#define HD 64
#define CC 512
#define BH 16            // BB*NH
#define NTILE 6          // TT/32
#define NPAIR 21         // NTILE*(NTILE+1)/2
#define SCALE 0.125f     // 1/sqrt(64)

// persistent device scratch (no allocations allowed)
__device__ __align__(16) float g_q [BH*TT*HD];
__device__ __align__(16) float g_k1[BH*TT*HD];
__device__ __align__(16) float g_k2[BH*TT*HD];
__device__ __align__(16) float g_Np[NTILE*BH*TT*HD];  // numerator partials per j-tile slab
__device__ __align__(16) float g_Zp[BH*NPAIR];        // Z partials per block
__device__ __align__(16) float g_y [BB*TT*CC];        // normalized y before final proj

// ---------------------------------------------------------------------------
// HMMA helpers
__device__ __forceinline__ unsigned int pkh2(float a, float b)
{
    __half2 h = __floats2half2_rn(a, b);
    return *reinterpret_cast<unsigned int*>(&h);
}

__device__ __forceinline__ void mma16816(float* d, const unsigned int* a, const unsigned int* b)
{
    asm volatile(
        "mma.sync.aligned.m16n8k16.row.col.f32.f16.f16.f32 "
        "{%0,%1,%2,%3}, {%4,%5,%6,%7}, {%8,%9}, {%0,%1,%2,%3};\n"
        : "+f"(d[0]), "+f"(d[1]), "+f"(d[2]), "+f"(d[3])
        : "r"(a[0]), "r"(a[1]), "r"(a[2]), "r"(a[3]), "r"(b[0]), "r"(b[1]));
}

// pack value as (hi fp16) | (lo fp16 << 16); hi+lo ~ 22-bit mantissa of f
__device__ __forceinline__ unsigned int splitpack(float f)
{
    __half h = __float2half_rn(f);
    __half l = __float2half_rn(f - __half2float(h));
    return (unsigned int)__half_as_ushort(h) | ((unsigned int)__half_as_ushort(l) << 16);
}

// ---------------------------------------------------------------------------
// split-fp16 GEMM core: C(64x64 tile at row0,col0) = A(row-major MxK) * B^T
// (B row-major NxK). acc[mt][nt][4] per standard m16n8 C layout.
__device__ __forceinline__ void gemm64_core(
    const float* __restrict__ A, const float* __restrict__ B,
    int row0, int col0, float (&acc)[2][2][4],
    unsigned int (*sA)[66], unsigned int (*sB)[66])
{
    const int tid = threadIdx.x;
    const int w  = tid >> 5, l = tid & 31;
    const int wm = w >> 2, wn = w & 3;
    const int g  = l >> 2, c2 = (l & 3) << 1;
    const int lr = tid >> 2, lc0 = (tid & 3) << 4;

    for (int kc = 0; kc < CC; kc += 64) {
        const float* ap = A + (row0 + lr)*CC + kc + lc0;
        const float* bp = B + (col0 + lr)*CC + kc + lc0;
        #pragma unroll
        for (int v = 0; v < 4; ++v) {
            float4 fa = *(const float4*)(ap + v*4);
            float4 fb = *(const float4*)(bp + v*4);
            sA[lr][lc0 + v*4 + 0] = splitpack(fa.x);
            sA[lr][lc0 + v*4 + 1] = splitpack(fa.y);
            sA[lr][lc0 + v*4 + 2] = splitpack(fa.z);
            sA[lr][lc0 + v*4 + 3] = splitpack(fa.w);
            sB[lr][lc0 + v*4 + 0] = splitpack(fb.x);
            sB[lr][lc0 + v*4 + 1] = splitpack(fb.y);
            sB[lr][lc0 + v*4 + 2] = splitpack(fb.z);
            sB[lr][lc0 + v*4 + 3] = splitpack(fb.w);
        }
        __syncthreads();
        #pragma unroll
        for (int ks = 0; ks < 4; ++ks) {
            const int k0 = ks*16 + c2;
            // A fragments (hi & lo) for both mt
            unsigned int ahi[2][4], alo[2][4];
            #pragma unroll
            for (int mt = 0; mt < 2; ++mt) {
                const int r = wm*32 + mt*16 + g;
                uint2 p0 = *(const uint2*)&sA[r    ][k0    ];
                uint2 p1 = *(const uint2*)&sA[r + 8][k0    ];
                uint2 p2 = *(const uint2*)&sA[r    ][k0 + 8];
                uint2 p3 = *(const uint2*)&sA[r + 8][k0 + 8];
                ahi[mt][0] = __byte_perm(p0.x, p0.y, 0x5410);
                alo[mt][0] = __byte_perm(p0.x, p0.y, 0x7632);
                ahi[mt][1] = __byte_perm(p1.x, p1.y, 0x5410);
                alo[mt][1] = __byte_perm(p1.x, p1.y, 0x7632);
                ahi[mt][2] = __byte_perm(p2.x, p2.y, 0x5410);
                alo[mt][2] = __byte_perm(p2.x, p2.y, 0x7632);
                ahi[mt][3] = __byte_perm(p3.x, p3.y, 0x5410);
                alo[mt][3] = __byte_perm(p3.x, p3.y, 0x7632);
            }
            #pragma unroll
            for (int nt = 0; nt < 2; ++nt) {
                const int n = wn*16 + nt*8 + g;
                uint2 q0 = *(const uint2*)&sB[n][k0    ];
                uint2 q1 = *(const uint2*)&sB[n][k0 + 8];
                unsigned int bhi[2], blo[2];
                bhi[0] = __byte_perm(q0.x, q0.y, 0x5410);
                blo[0] = __byte_perm(q0.x, q0.y, 0x7632);
                bhi[1] = __byte_perm(q1.x, q1.y, 0x5410);
                blo[1] = __byte_perm(q1.x, q1.y, 0x7632);
                #pragma unroll
                for (int mt = 0; mt < 2; ++mt) {
                    mma16816(acc[mt][nt], ahi[mt], bhi);
                    mma16816(acc[mt][nt], ahi[mt], blo);
                    mma16816(acc[mt][nt], alo[mt], bhi);
                }
            }
        }
        __syncthreads();
    }
}

// ---------------------------------------------------------------------------
// projections: q = x@W0^T, k1 = x@W1^T, k2 = x@W2^T, stored [bh][t][d]
__global__ __launch_bounds__(256)
void proj_kernel(const float* __restrict__ x, const float* __restrict__ W0,
                 const float* __restrict__ W1, const float* __restrict__ W2)
{
    __shared__ __align__(16) unsigned int sA[64][66];
    __shared__ __align__(16) unsigned int sB[64][66];
    const float* W   = (blockIdx.z == 0) ? W0 : (blockIdx.z == 1) ? W1 : W2;
    float*       dst = (blockIdx.z == 0) ? g_q : (blockIdx.z == 1) ? g_k1 : g_k2;
    const int row0 = blockIdx.y * 64, col0 = blockIdx.x * 64;
    float acc[2][2][4];
    #pragma unroll
    for (int a = 0; a < 2; ++a)
        #pragma unroll
        for (int b = 0; b < 2; ++b)
            #pragma unroll
            for (int c = 0; c < 4; ++c) acc[a][b][c] = 0.f;
    gemm64_core(x, W, row0, col0, acc, sA, sB);

    const int w = threadIdx.x >> 5, l = threadIdx.x & 31;
    const int wm = w >> 2, wn = w & 3;
    #pragma unroll
    for (int mt = 0; mt < 2; ++mt)
        #pragma unroll
        for (int nt = 0; nt < 2; ++nt) {
            const int col = col0 + wn*16 + nt*8 + ((l & 3) << 1);
            const int h = col >> 6, d = col & 63;
            #pragma unroll
            for (int rh = 0; rh < 2; ++rh) {
                const int row = row0 + wm*32 + mt*16 + (l >> 2) + rh*8;
                const int b = row / TT, t = row - b*TT;
                float2 v = make_float2(acc[mt][nt][rh*2], acc[mt][nt][rh*2 + 1]);
                *(float2*)&dst[((b*NH + h)*TT + t)*HD + d] = v;
            }
        }
}

// ---------------------------------------------------------------------------
// one 32-token k-chunk: mma, mask+exp, j-fold, PV — all within one warp.
// MJ: ti==tj (j<=i mask active); MK: kc==tj (k<=j mask active).
template<bool MJ, bool MK>
__device__ __forceinline__ void do_chunk(
    int n0, int ig, int j0, int g, int q2, int lane,
    const unsigned int (&afr)[2][4][4], const __half (*k2s)[72],
    float& zacc, float& nacc0, float& nacc1)
{
    #pragma unroll
    for (int nt = 0; nt < 4; ++nt) {
        // whole 8-token group above i on corner-diagonal chunks: fully masked
        if (MJ && MK && (n0 + nt*8) > ig) continue;
        const int tok = n0 + nt*8 + g;
        unsigned int bfr[4][2];
        #pragma unroll
        for (int ks = 0; ks < 4; ++ks) {
            bfr[ks][0] = *(const unsigned int*)&k2s[tok][ks*16 + q2];
            bfr[ks][1] = *(const unsigned int*)&k2s[tok][ks*16 + q2 + 8];
        }
        float Qf0 = 0.f, Qf1 = 0.f;
        #pragma unroll
        for (int mt = 0; mt < 2; ++mt) {
            if (MJ && (j0 + mt*16) > ig) continue;  // whole 16-row group above i
            float acc[4] = {0.f, 0.f, 0.f, 0.f};
            #pragma unroll
            for (int ks = 0; ks < 4; ++ks) mma16816(acc, afr[mt][ks], bfr[ks]);
            const int jlo = j0 + mt*16 + g, jhi = jlo + 8;
            const int k0  = n0 + nt*8 + q2, k1 = k0 + 1;
            bool v0 = (!MJ || jlo <= ig) && (!MK || k0 <= jlo);
            bool v1 = (!MJ || jlo <= ig) && (!MK || k1 <= jlo);
            bool v2 = (!MJ || jhi <= ig) && (!MK || k0 <= jhi);
            bool v3 = (!MJ || jhi <= ig) && (!MK || k1 <= jhi);
            float p0 = v0 ? __expf(acc[0]*SCALE) : 0.f;
            float p1 = v1 ? __expf(acc[1]*SCALE) : 0.f;
            float p2 = v2 ? __expf(acc[2]*SCALE) : 0.f;
            float p3 = v3 ? __expf(acc[3]*SCALE) : 0.f;
            zacc += (p0 + p1) + (p2 + p3);
            Qf0 += p0 + p2;
            Qf1 += p1 + p3;
        }
        // fold across the 8 j row-groups (lanes differing in bits 2..4)
        #pragma unroll
        for (int m = 4; m <= 16; m <<= 1) {
            Qf0 += __shfl_xor_sync(0xffffffffu, Qf0, m);
            Qf1 += __shfl_xor_sync(0xffffffffu, Qf1, m);
        }
        // PV for this nt's 8 tokens: nacc[d] += Q[k] * k2[k][d]
        #pragma unroll
        for (int kk = 0; kk < 8; ++kk) {
            float qv = __shfl_sync(0xffffffffu, (kk & 1) ? Qf1 : Qf0, kk >> 1);
            __half2 hv = *(const __half2*)&k2s[n0 + nt*8 + kk][2*lane];
            float2 fv = __half22float2(hv);
            nacc0 += qv * fv.x;
            nacc1 += qv * fv.y;
        }
    }
}

// ---------------------------------------------------------------------------
// fused trilinear scores (HMMA) + exp + j-fold + PV.
// block = (bh, i-tile, j-tile<=i-tile); 336 blocks. Warp w owns i = isub*8+w.
__global__ __launch_bounds__(256)
void attn_kernel()
{
    __shared__ float  qs [32][65];
    __shared__ float  k1s[32][65];
    __shared__ __half k2s[192][72];
    __shared__ float  zred[8];

    const int bh = blockIdx.x & 15;
    const int p  = blockIdx.x >> 4;
    int tj = NTILE - 1, start = 0, cnt = 1;
    while (p >= start + cnt) { start += cnt; --tj; ++cnt; }
    const int ti = tj + (p - start);
    const int i0 = ti * 32, j0 = tj * 32;
    const int tid  = threadIdx.x;
    const int w    = tid >> 5, lane = tid & 31;
    const int g    = lane >> 2, q2 = (lane & 3) << 1;
    const bool diag = (ti == tj);

    // load q/k1 tiles fp32; k2 (all tokens 0..(tj+1)*32) as fp16
    {
        const float* qg  = g_q  + (bh*TT + i0)*HD;
        const float* k1g = g_k1 + (bh*TT + j0)*HD;
        for (int l = tid; l < 32*64; l += 256) {
            int r = l >> 6, d = l & 63;
            qs[r][d]  = qg[r*HD + d];
            k1s[r][d] = k1g[r*HD + d];
        }
        const int ntok = (tj + 1) * 32;
        const float* k2g = g_k2 + bh*TT*HD;
        for (int l = tid; l < ntok*16; l += 256) {
            int r = l >> 4, c4 = (l & 15) << 2;
            float4 v = *(const float4*)(k2g + r*HD + c4);
            *(__half2*)&k2s[r][c4]     = __floats2half2_rn(v.x, v.y);
            *(__half2*)&k2s[r][c4 + 2] = __floats2half2_rn(v.z, v.w);
        }
    }
    __syncthreads();

    float zacc = 0.f;

    for (int isub = 0; isub < 4; ++isub) {
        const int il = isub*8 + w;      // this warp's i within the tile
        const int ig = i0 + il;

        // build A fragments in registers: W[j,d] = q[i,d] * k1[j,d] (fp16)
        unsigned int afr[2][4][4];
        #pragma unroll
        for (int mt = 0; mt < 2; ++mt) {
            const int jlo = mt*16 + g, jhi = jlo + 8;
            #pragma unroll
            for (int ks = 0; ks < 4; ++ks) {
                const int d0 = ks*16 + q2;
                float qa = qs[il][d0],   qb = qs[il][d0+1];
                float qc = qs[il][d0+8], qd = qs[il][d0+9];
                afr[mt][ks][0] = pkh2(qa*k1s[jlo][d0],   qb*k1s[jlo][d0+1]);
                afr[mt][ks][1] = pkh2(qa*k1s[jhi][d0],   qb*k1s[jhi][d0+1]);
                afr[mt][ks][2] = pkh2(qc*k1s[jlo][d0+8], qd*k1s[jlo][d0+9]);
                afr[mt][ks][3] = pkh2(qc*k1s[jhi][d0+8], qd*k1s[jhi][d0+9]);
            }
        }

        float nacc0 = 0.f, nacc1 = 0.f;
        for (int kc = 0; kc <= tj; ++kc) {
            const int n0 = kc * 32;
            const bool mk = (kc == tj);
            if (diag) {
                if (mk) do_chunk<true ,true >(n0, ig, j0, g, q2, lane, afr, k2s, zacc, nacc0, nacc1);
                else    do_chunk<true ,false>(n0, ig, j0, g, q2, lane, afr, k2s, zacc, nacc0, nacc1);
            } else {
                if (mk) do_chunk<false,true >(n0, ig, j0, g, q2, lane, afr, k2s, zacc, nacc0, nacc1);
                else    do_chunk<false,false>(n0, ig, j0, g, q2, lane, afr, k2s, zacc, nacc0, nacc1);
            }
        }
        // write numerator partial row (unique writer per (tj-slab, bh, i))
        float* np = g_Np + ((tj*BH + bh)*TT + ig)*HD + 2*lane;
        np[0] = nacc0;
        np[1] = nacc1;
    }

    // Z partial: block-reduce
    #pragma unroll
    for (int m = 16; m >= 1; m >>= 1)
        zacc += __shfl_xor_sync(0xffffffffu, zacc, m);
    if (lane == 0) zred[w] = zacc;
    __syncthreads();
    if (tid == 0) {
        float z = 0.f;
        #pragma unroll
        for (int ww = 0; ww < 8; ++ww) z += zred[ww];
        g_Zp[bh*NPAIR + p] = z;
    }
}

// ---------------------------------------------------------------------------
// y[b,t,h*64+d] = (sum of valid slab partials) / Z[bh]   (float4 vectorized)
__global__ __launch_bounds__(256)
void finalize_y()
{
    __shared__ float invZ[BH];
    const int tid = threadIdx.x;
    if (tid < BH) {
        float z = 0.f;
        #pragma unroll
        for (int pp = 0; pp < NPAIR; ++pp) z += g_Zp[tid*NPAIR + pp];
        invZ[tid] = 1.f / z;
    }
    __syncthreads();
    int e  = blockIdx.x * 256 + tid;    // < BB*TT*CC/4 = 49152
    int c4 = e & 127;                    // float4 index within C row
    int r  = e >> 7;                     // (b,t) row
    int b = r / TT, t = r - b*TT;
    int h = c4 >> 4, d4 = c4 & 15;
    int bh = b*NH + h;
    float4 acc = make_float4(0.f, 0.f, 0.f, 0.f);
    const int smax = t >> 5;             // slabs tj <= t/32 are valid for this row
    for (int s = 0; s <= smax; ++s) {
        float4 v = *(const float4*)&g_Np[((s*BH + bh)*TT + t)*HD + d4*4];
        acc.x += v.x; acc.y += v.y; acc.z += v.z; acc.w += v.w;
    }
    float iz = invZ[bh];
    acc.x *= iz; acc.y *= iz; acc.z *= iz; acc.w *= iz;
    *(float4*)&g_y[r*CC + c4*4] = acc;
}

// ---------------------------------------------------------------------------
// out = y @ Wp^T  (split-fp16 HMMA)
__global__ __launch_bounds__(256)
void out_kernel(const float* __restrict__ Wp, float* __restrict__ out)
{
    __shared__ __align__(16) unsigned int sA[64][66];
    __shared__ __align__(16) unsigned int sB[64][66];
    const int row0 = blockIdx.y * 64, col0 = blockIdx.x * 64;
    float acc[2][2][4];
    #pragma unroll
    for (int a = 0; a < 2; ++a)
        #pragma unroll
        for (int b = 0; b < 2; ++b)
            #pragma unroll
            for (int c = 0; c < 4; ++c) acc[a][b][c] = 0.f;
    gemm64_core(g_y, Wp, row0, col0, acc, sA, sB);

    const int w = threadIdx.x >> 5, l = threadIdx.x & 31;
    const int wm = w >> 2, wn = w & 3;
    #pragma unroll
    for (int mt = 0; mt < 2; ++mt)
        #pragma unroll
        for (int nt = 0; nt < 2; ++nt) {
            const int col = col0 + wn*16 + nt*8 + ((l & 3) << 1);
            #pragma unroll
            for (int rh = 0; rh < 2; ++rh) {
                const int row = row0 + wm*32 + mt*16 + (l >> 2) + rh*8;
                float2 v = make_float2(acc[mt][nt][rh*2], acc[mt][nt][rh*2 + 1]);
                *(float2*)&out[row*CC + col] = v;
            }
        }
}

// ---------------------------------------------------------------------------
extern "C" void kernel_launch(void* const* d_in, const int* in_sizes, int n_in,
                              void* d_out, int out_size)
{
    const float* x  = (const float*)d_in[0];
    const float* W0 = (const float*)d_in[1];
    const float* W1 = (const float*)d_in[2];
    const float* W2 = (const float*)d_in[3];
    const float* Wp = (const float*)d_in[4];
    float* out = (float*)d_out;

    dim3 pg(CC/64, (BB*TT)/64, 3);
    proj_kernel<<<pg, 256>>>(x, W0, W1, W2);
    attn_kernel<<<NPAIR*BH, 256>>>();
    finalize_y<<<(BB*TT*CC/4)/256, 256>>>();
    dim3 og(CC/64, (BB*TT)/64);
    out_kernel<<<og, 256>>>(Wp, out);
}

// round 6
// speedup vs baseline: 2.5661x; 1.1778x over previous
#include <cuda_runtime.h>
#include <cuda_fp16.h>
#include <stdint.h>

#define BB 2
#define NH 8
#define TT 192
#define HD 64
#define CC 512
#define BH 16            // BB*NH
#define NTILE 6          // TT/32
#define NPAIR 21         // NTILE*(NTILE+1)/2
#define SCALE 0.125f     // 1/sqrt(64)
#define XN (BB*TT*CC)    // 196608
#define WN (CC*CC)       // 262144

// persistent device scratch (no allocations allowed)
__device__ __align__(16) float    g_q [BH*TT*HD];
__device__ __align__(16) float    g_k1[BH*TT*HD];
__device__ __align__(16) float    g_k2[BH*TT*HD];
__device__ __align__(16) float    g_Np[NTILE*BH*TT*HD];
__device__ __align__(16) float    g_Zp[BH*NPAIR];
__device__ __align__(16) unsigned g_xs[XN];        // x packed split-fp16
__device__ __align__(16) unsigned g_Ws[4][WN];     // W0,W1,W2,Wp packed
__device__ __align__(16) unsigned g_ys[XN];        // normalized y packed
__device__ __align__(16) float    g_outp[2][XN];   // out K-split partials

// ---------------------------------------------------------------------------
// HMMA helpers
__device__ __forceinline__ unsigned int pkh2(float a, float b)
{
    __half2 h = __floats2half2_rn(a, b);
    return *reinterpret_cast<unsigned int*>(&h);
}

__device__ __forceinline__ void mma16816(float* d, const unsigned int* a, const unsigned int* b)
{
    asm volatile(
        "mma.sync.aligned.m16n8k16.row.col.f32.f16.f16.f32 "
        "{%0,%1,%2,%3}, {%4,%5,%6,%7}, {%8,%9}, {%0,%1,%2,%3};\n"
        : "+f"(d[0]), "+f"(d[1]), "+f"(d[2]), "+f"(d[3])
        : "r"(a[0]), "r"(a[1]), "r"(a[2]), "r"(a[3]), "r"(b[0]), "r"(b[1]));
}

// pack value as (hi fp16) | (lo fp16 << 16); hi+lo ~ 22-bit mantissa of f
__device__ __forceinline__ unsigned int splitpack(float f)
{
    __half h = __float2half_rn(f);
    __half l = __float2half_rn(f - __half2float(h));
    return (unsigned int)__half_as_ushort(h) | ((unsigned int)__half_as_ushort(l) << 16);
}

// ---------------------------------------------------------------------------
// convert x + all four weight matrices to packed split-fp16 (float4-vectorized)
__global__ __launch_bounds__(256)
void cvt_kernel(const float* __restrict__ x,  const float* __restrict__ W0,
                const float* __restrict__ W1, const float* __restrict__ W2,
                const float* __restrict__ Wp)
{
    int i4 = (blockIdx.x * 256 + threadIdx.x) * 4;   // exact: 1216*256*4 = XN+4*WN
    const float* src;
    unsigned*    dst;
    if (i4 < XN) {
        src = x + i4;
        dst = g_xs + i4;
    } else {
        int o = i4 - XN;
        int r = o >> 18;          // WN = 2^18
        o &= (WN - 1);
        src = (r == 0 ? W0 : r == 1 ? W1 : r == 2 ? W2 : Wp) + o;
        dst = g_Ws[r] + o;
    }
    float4 v = *(const float4*)src;
    uint4 u;
    u.x = splitpack(v.x); u.y = splitpack(v.y);
    u.z = splitpack(v.z); u.w = splitpack(v.w);
    *(uint4*)dst = u;
}

// ---------------------------------------------------------------------------
// split-fp16 GEMM core on pre-packed operands:
// C(64x64 @ row0,col0) += A(rows, packed) * B(rows, packed)^T over K [kb, ke)
// NOTE: smem row stride 68 uints (272B) keeps every row 16B-aligned for STS.128
__device__ __forceinline__ void gemm64_core(
    const unsigned* __restrict__ A, const unsigned* __restrict__ B,
    int row0, int col0, int kb, int ke, float (&acc)[2][2][4],
    unsigned (*sA)[68], unsigned (*sB)[68])
{
    const int tid = threadIdx.x;
    const int w  = tid >> 5, l = tid & 31;
    const int wm = w >> 2, wn = w & 3;
    const int g  = l >> 2, c2 = (l & 3) << 1;
    const int lr = tid >> 2, lc0 = (tid & 3) << 4;

    for (int kc = kb; kc < ke; kc += 64) {
        const unsigned* ap = A + (row0 + lr)*CC + kc + lc0;
        const unsigned* bp = B + (col0 + lr)*CC + kc + lc0;
        #pragma unroll
        for (int v = 0; v < 4; ++v) {
            *(uint4*)&sA[lr][lc0 + v*4] = *(const uint4*)(ap + v*4);
            *(uint4*)&sB[lr][lc0 + v*4] = *(const uint4*)(bp + v*4);
        }
        __syncthreads();
        #pragma unroll
        for (int ks = 0; ks < 4; ++ks) {
            const int k0 = ks*16 + c2;
            unsigned ahi[2][4], alo[2][4];
            #pragma unroll
            for (int mt = 0; mt < 2; ++mt) {
                const int r = wm*32 + mt*16 + g;
                uint2 p0 = *(const uint2*)&sA[r    ][k0    ];
                uint2 p1 = *(const uint2*)&sA[r + 8][k0    ];
                uint2 p2 = *(const uint2*)&sA[r    ][k0 + 8];
                uint2 p3 = *(const uint2*)&sA[r + 8][k0 + 8];
                ahi[mt][0] = __byte_perm(p0.x, p0.y, 0x5410);
                alo[mt][0] = __byte_perm(p0.x, p0.y, 0x7632);
                ahi[mt][1] = __byte_perm(p1.x, p1.y, 0x5410);
                alo[mt][1] = __byte_perm(p1.x, p1.y, 0x7632);
                ahi[mt][2] = __byte_perm(p2.x, p2.y, 0x5410);
                alo[mt][2] = __byte_perm(p2.x, p2.y, 0x7632);
                ahi[mt][3] = __byte_perm(p3.x, p3.y, 0x5410);
                alo[mt][3] = __byte_perm(p3.x, p3.y, 0x7632);
            }
            #pragma unroll
            for (int nt = 0; nt < 2; ++nt) {
                const int n = wn*16 + nt*8 + g;
                uint2 q0 = *(const uint2*)&sB[n][k0    ];
                uint2 q1 = *(const uint2*)&sB[n][k0 + 8];
                unsigned bhi[2], blo[2];
                bhi[0] = __byte_perm(q0.x, q0.y, 0x5410);
                blo[0] = __byte_perm(q0.x, q0.y, 0x7632);
                bhi[1] = __byte_perm(q1.x, q1.y, 0x5410);
                blo[1] = __byte_perm(q1.x, q1.y, 0x7632);
                #pragma unroll
                for (int mt = 0; mt < 2; ++mt) {
                    mma16816(acc[mt][nt], ahi[mt], bhi);
                    mma16816(acc[mt][nt], ahi[mt], blo);
                    mma16816(acc[mt][nt], alo[mt], bhi);
                }
            }
        }
        __syncthreads();
    }
}

// ---------------------------------------------------------------------------
// projections: q = x@W0^T, k1 = x@W1^T, k2 = x@W2^T, stored [bh][t][d]
__global__ __launch_bounds__(256)
void proj_kernel()
{
    __shared__ __align__(16) unsigned sA[64][68];
    __shared__ __align__(16) unsigned sB[64][68];
    float* dst = (blockIdx.z == 0) ? g_q : (blockIdx.z == 1) ? g_k1 : g_k2;
    const int row0 = blockIdx.y * 64, col0 = blockIdx.x * 64;
    float acc[2][2][4];
    #pragma unroll
    for (int a = 0; a < 2; ++a)
        #pragma unroll
        for (int b = 0; b < 2; ++b)
            #pragma unroll
            for (int c = 0; c < 4; ++c) acc[a][b][c] = 0.f;
    gemm64_core(g_xs, g_Ws[blockIdx.z], row0, col0, 0, CC, acc, sA, sB);

    const int w = threadIdx.x >> 5, l = threadIdx.x & 31;
    const int wm = w >> 2, wn = w & 3;
    #pragma unroll
    for (int mt = 0; mt < 2; ++mt)
        #pragma unroll
        for (int nt = 0; nt < 2; ++nt) {
            const int col = col0 + wn*16 + nt*8 + ((l & 3) << 1);
            const int h = col >> 6, d = col & 63;
            #pragma unroll
            for (int rh = 0; rh < 2; ++rh) {
                const int row = row0 + wm*32 + mt*16 + (l >> 2) + rh*8;
                const int b = row / TT, t = row - b*TT;
                float2 v = make_float2(acc[mt][nt][rh*2], acc[mt][nt][rh*2 + 1]);
                *(float2*)&dst[((b*NH + h)*TT + t)*HD + d] = v;
            }
        }
}

// ---------------------------------------------------------------------------
// one 32-token k-chunk: mma, mask+exp, j-fold, PV — all within one warp.
template<bool MJ, bool MK>
__device__ __forceinline__ void do_chunk(
    int n0, int ig, int j0, int g, int q2, int lane,
    const unsigned int (&afr)[2][4][4], const __half (*k2s)[72],
    float& zacc, float& nacc0, float& nacc1)
{
    #pragma unroll
    for (int nt = 0; nt < 4; ++nt) {
        if (MJ && MK && (n0 + nt*8) > ig) continue;
        const int tok = n0 + nt*8 + g;
        unsigned int bfr[4][2];
        #pragma unroll
        for (int ks = 0; ks < 4; ++ks) {
            bfr[ks][0] = *(const unsigned int*)&k2s[tok][ks*16 + q2];
            bfr[ks][1] = *(const unsigned int*)&k2s[tok][ks*16 + q2 + 8];
        }
        float Qf0 = 0.f, Qf1 = 0.f;
        #pragma unroll
        for (int mt = 0; mt < 2; ++mt) {
            if (MJ && (j0 + mt*16) > ig) continue;
            float acc[4] = {0.f, 0.f, 0.f, 0.f};
            #pragma unroll
            for (int ks = 0; ks < 4; ++ks) mma16816(acc, afr[mt][ks], bfr[ks]);
            const int jlo = j0 + mt*16 + g, jhi = jlo + 8;
            const int k0  = n0 + nt*8 + q2, k1 = k0 + 1;
            bool v0 = (!MJ || jlo <= ig) && (!MK || k0 <= jlo);
            bool v1 = (!MJ || jlo <= ig) && (!MK || k1 <= jlo);
            bool v2 = (!MJ || jhi <= ig) && (!MK || k0 <= jhi);
            bool v3 = (!MJ || jhi <= ig) && (!MK || k1 <= jhi);
            float p0 = v0 ? __expf(acc[0]*SCALE) : 0.f;
            float p1 = v1 ? __expf(acc[1]*SCALE) : 0.f;
            float p2 = v2 ? __expf(acc[2]*SCALE) : 0.f;
            float p3 = v3 ? __expf(acc[3]*SCALE) : 0.f;
            zacc += (p0 + p1) + (p2 + p3);
            Qf0 += p0 + p2;
            Qf1 += p1 + p3;
        }
        // fold across the 8 j row-groups (lanes differing in bits 2..4)
        #pragma unroll
        for (int m = 4; m <= 16; m <<= 1) {
            Qf0 += __shfl_xor_sync(0xffffffffu, Qf0, m);
            Qf1 += __shfl_xor_sync(0xffffffffu, Qf1, m);
        }
        // PV: broadcast folded (Qf0,Qf1) as one packed half2 per token-pair
        unsigned qp = pkh2(Qf0, Qf1);
        #pragma unroll
        for (int kk2 = 0; kk2 < 4; ++kk2) {
            unsigned u = __shfl_sync(0xffffffffu, qp, kk2);
            float2 qf = __half22float2(*reinterpret_cast<__half2*>(&u));
            const int t0 = n0 + nt*8 + kk2*2;
            float2 f0 = __half22float2(*(const __half2*)&k2s[t0    ][2*lane]);
            float2 f1 = __half22float2(*(const __half2*)&k2s[t0 + 1][2*lane]);
            nacc0 += qf.x*f0.x + qf.y*f1.x;
            nacc1 += qf.x*f0.y + qf.y*f1.y;
        }
    }
}

// ---------------------------------------------------------------------------
// fused trilinear scores (HMMA) + exp + j-fold + PV.
__global__ __launch_bounds__(256)
void attn_kernel()
{
    __shared__ float  qs [32][65];
    __shared__ float  k1s[32][65];
    __shared__ __half k2s[192][72];
    __shared__ float  zred[8];

    const int bh = blockIdx.x & 15;
    const int p  = blockIdx.x >> 4;
    int tj = NTILE - 1, start = 0, cnt = 1;
    while (p >= start + cnt) { start += cnt; --tj; ++cnt; }
    const int ti = tj + (p - start);
    const int i0 = ti * 32, j0 = tj * 32;
    const int tid  = threadIdx.x;
    const int w    = tid >> 5, lane = tid & 31;
    const int g    = lane >> 2, q2 = (lane & 3) << 1;
    const bool diag = (ti == tj);

    {
        const float* qg  = g_q  + (bh*TT + i0)*HD;
        const float* k1g = g_k1 + (bh*TT + j0)*HD;
        for (int l = tid; l < 32*64; l += 256) {
            int r = l >> 6, d = l & 63;
            qs[r][d]  = qg[r*HD + d];
            k1s[r][d] = k1g[r*HD + d];
        }
        const int ntok = (tj + 1) * 32;
        const float* k2g = g_k2 + bh*TT*HD;
        for (int l = tid; l < ntok*16; l += 256) {
            int r = l >> 4, c4 = (l & 15) << 2;
            float4 v = *(const float4*)(k2g + r*HD + c4);
            *(__half2*)&k2s[r][c4]     = __floats2half2_rn(v.x, v.y);
            *(__half2*)&k2s[r][c4 + 2] = __floats2half2_rn(v.z, v.w);
        }
    }
    __syncthreads();

    float zacc = 0.f;

    for (int isub = 0; isub < 4; ++isub) {
        const int il = isub*8 + w;
        const int ig = i0 + il;

        unsigned int afr[2][4][4];
        #pragma unroll
        for (int mt = 0; mt < 2; ++mt) {
            const int jlo = mt*16 + g, jhi = jlo + 8;
            #pragma unroll
            for (int ks = 0; ks < 4; ++ks) {
                const int d0 = ks*16 + q2;
                float qa = qs[il][d0],   qb = qs[il][d0+1];
                float qc = qs[il][d0+8], qd = qs[il][d0+9];
                afr[mt][ks][0] = pkh2(qa*k1s[jlo][d0],   qb*k1s[jlo][d0+1]);
                afr[mt][ks][1] = pkh2(qa*k1s[jhi][d0],   qb*k1s[jhi][d0+1]);
                afr[mt][ks][2] = pkh2(qc*k1s[jlo][d0+8], qd*k1s[jlo][d0+9]);
                afr[mt][ks][3] = pkh2(qc*k1s[jhi][d0+8], qd*k1s[jhi][d0+9]);
            }
        }

        float nacc0 = 0.f, nacc1 = 0.f;
        for (int kc = 0; kc <= tj; ++kc) {
            const int n0 = kc * 32;
            const bool mk = (kc == tj);
            if (diag) {
                if (mk) do_chunk<true ,true >(n0, ig, j0, g, q2, lane, afr, k2s, zacc, nacc0, nacc1);
                else    do_chunk<true ,false>(n0, ig, j0, g, q2, lane, afr, k2s, zacc, nacc0, nacc1);
            } else {
                if (mk) do_chunk<false,true >(n0, ig, j0, g, q2, lane, afr, k2s, zacc, nacc0, nacc1);
                else    do_chunk<false,false>(n0, ig, j0, g, q2, lane, afr, k2s, zacc, nacc0, nacc1);
            }
        }
        float* np = g_Np + ((tj*BH + bh)*TT + ig)*HD + 2*lane;
        np[0] = nacc0;
        np[1] = nacc1;
    }

    #pragma unroll
    for (int m = 16; m >= 1; m >>= 1)
        zacc += __shfl_xor_sync(0xffffffffu, zacc, m);
    if (lane == 0) zred[w] = zacc;
    __syncthreads();
    if (tid == 0) {
        float z = 0.f;
        #pragma unroll
        for (int ww = 0; ww < 8; ++ww) z += zred[ww];
        g_Zp[bh*NPAIR + p] = z;
    }
}

// ---------------------------------------------------------------------------
// y = (sum of valid slab partials)/Z, written PACKED split-fp16 for out GEMM
__global__ __launch_bounds__(256)
void finalize_y()
{
    __shared__ float invZ[BH];
    const int tid = threadIdx.x;
    if (tid < BH) {
        float z = 0.f;
        #pragma unroll
        for (int pp = 0; pp < NPAIR; ++pp) z += g_Zp[tid*NPAIR + pp];
        invZ[tid] = 1.f / z;
    }
    __syncthreads();
    int e  = blockIdx.x * 256 + tid;    // < XN/4 = 49152
    int c4 = e & 127;
    int r  = e >> 7;
    int b = r / TT, t = r - b*TT;
    int h = c4 >> 4, d4 = c4 & 15;
    int bh = b*NH + h;
    float4 acc = make_float4(0.f, 0.f, 0.f, 0.f);
    const int smax = t >> 5;
    for (int s = 0; s <= smax; ++s) {
        float4 v = *(const float4*)&g_Np[((s*BH + bh)*TT + t)*HD + d4*4];
        acc.x += v.x; acc.y += v.y; acc.z += v.z; acc.w += v.w;
    }
    float iz = invZ[bh];
    uint4 u;
    u.x = splitpack(acc.x * iz); u.y = splitpack(acc.y * iz);
    u.z = splitpack(acc.z * iz); u.w = splitpack(acc.w * iz);
    *(uint4*)&g_ys[r*CC + c4*4] = u;
}

// ---------------------------------------------------------------------------
// out partials: K-split halves of y @ Wp^T
__global__ __launch_bounds__(256)
void out_kernel()
{
    __shared__ __align__(16) unsigned sA[64][68];
    __shared__ __align__(16) unsigned sB[64][68];
    const int row0 = blockIdx.y * 64, col0 = blockIdx.x * 64;
    const int z = blockIdx.z;
    float acc[2][2][4];
    #pragma unroll
    for (int a = 0; a < 2; ++a)
        #pragma unroll
        for (int b = 0; b < 2; ++b)
            #pragma unroll
            for (int c = 0; c < 4; ++c) acc[a][b][c] = 0.f;
    gemm64_core(g_ys, g_Ws[3], row0, col0, z*(CC/2), (z+1)*(CC/2), acc, sA, sB);

    const int w = threadIdx.x >> 5, l = threadIdx.x & 31;
    const int wm = w >> 2, wn = w & 3;
    float* op = g_outp[z];
    #pragma unroll
    for (int mt = 0; mt < 2; ++mt)
        #pragma unroll
        for (int nt = 0; nt < 2; ++nt) {
            const int col = col0 + wn*16 + nt*8 + ((l & 3) << 1);
            #pragma unroll
            for (int rh = 0; rh < 2; ++rh) {
                const int row = row0 + wm*32 + mt*16 + (l >> 2) + rh*8;
                float2 v = make_float2(acc[mt][nt][rh*2], acc[mt][nt][rh*2 + 1]);
                *(float2*)&op[row*CC + col] = v;
            }
        }
}

// ---------------------------------------------------------------------------
__global__ __launch_bounds__(256)
void reduce_out(float* __restrict__ out)
{
    int e4 = (blockIdx.x * 256 + threadIdx.x) * 4;   // < XN
    float4 a = *(const float4*)&g_outp[0][e4];
    float4 b = *(const float4*)&g_outp[1][e4];
    float4 r = make_float4(a.x + b.x, a.y + b.y, a.z + b.z, a.w + b.w);
    *(float4*)&out[e4] = r;
}

// ---------------------------------------------------------------------------
extern "C" void kernel_launch(void* const* d_in, const int* in_sizes, int n_in,
                              void* d_out, int out_size)
{
    const float* x  = (const float*)d_in[0];
    const float* W0 = (const float*)d_in[1];
    const float* W1 = (const float*)d_in[2];
    const float* W2 = (const float*)d_in[3];
    const float* Wp = (const float*)d_in[4];
    float* out = (float*)d_out;

    cvt_kernel<<<(XN + 4*WN)/(256*4), 256>>>(x, W0, W1, W2, Wp);
    dim3 pg(CC/64, (BB*TT)/64, 3);
    proj_kernel<<<pg, 256>>>();
    attn_kernel<<<NPAIR*BH, 256>>>();
    finalize_y<<<(XN/4)/256, 256>>>();
    dim3 og(CC/64, (BB*TT)/64, 2);
    out_kernel<<<og, 256>>>();
    reduce_out<<<(XN/4)/256, 256>>>(out);
}